// round 9
// baseline (speedup 1.0000x reference)
#include <cuda_runtime.h>
#include <cuda_fp16.h>
#include <math.h>
#include <stdint.h>

#define B_   2
#define P_   8192
#define NB_  24
#define C1_  32
#define C2_  32
#define K_   13
#define A_   12
#define STEPS2_ 104              // 48-ca steps (13 k x 8)
#define WT_HALVES (K_*2*8*9216)  // 1,916,928

// smem byte offsets
#define SA_B    0                // 2 stages x 128 x 112B  = 28672 B
#define SB_B    28672            // 3 stages x 18432 B     = 55296 B
#define SACC_B  83968            // 128 x 196 floats       = 100352 B
#define SMEM_BYTES 184320

#define NTHR_ 768                // 24 warps: wm = wid&3 (32 rows), wn = wid>>2 (32 cols)

// ---------------- device scratch ----------------
__device__ __align__(16) __half g_WTh[WT_HALVES];   // fp16 B, fragment-ordered (3.8MB)
__device__ __align__(16) float g_md[B_*P_*3];
__device__ __align__(16) float g_kpo[C2_*K_*3];
__device__ __align__(16) float g_be[C2_*A_];

// ---------------- helpers ----------------
__device__ __forceinline__ void cp16(void* dst, const void* src) {
    uint32_t a;
    asm("{ .reg .u64 t; cvta.to.shared.u64 t, %1; cvt.u32.u64 %0, t; }" : "=r"(a) : "l"(dst));
    asm volatile("cp.async.cg.shared.global [%0], [%1], 16;" :: "r"(a), "l"(src));
}
#define CP_COMMIT() asm volatile("cp.async.commit_group;" ::: "memory")
#define CP_WAIT1()  asm volatile("cp.async.wait_group 1;" ::: "memory")

__device__ __forceinline__ void mma16(float* d, const uint32_t* a, uint32_t b0, uint32_t b1) {
    asm volatile(
        "mma.sync.aligned.m16n8k16.row.col.f32.f16.f16.f32 "
        "{%0,%1,%2,%3}, {%4,%5,%6,%7}, {%8,%9}, {%0,%1,%2,%3};"
        : "+f"(d[0]), "+f"(d[1]), "+f"(d[2]), "+f"(d[3])
        : "r"(a[0]), "r"(a[1]), "r"(a[2]), "r"(a[3]), "r"(b0), "r"(b1));
}
__device__ __forceinline__ void ldsm4(uint32_t* r, uint32_t addr) {
    asm volatile("ldmatrix.sync.aligned.m8n8.x4.shared.b16 {%0,%1,%2,%3}, [%4];"
        : "=r"(r[0]), "=r"(r[1]), "=r"(r[2]), "=r"(r[3]) : "r"(addr));
}
__device__ __forceinline__ uint32_t packh2(float x, float y) {
    uint32_t u;
    asm("cvt.rn.f16x2.f32 %0, %2, %1;" : "=r"(u) : "f"(x), "f"(y));
    return u;
}
__device__ __forceinline__ uint32_t smem_addr(const void* p) {
    uint32_t a;
    asm("{ .reg .u64 t; cvta.to.shared.u64 t, %1; cvt.u32.u64 %0, t; }" : "=r"(a) : "l"(p));
    return a;
}

// ---------------- prep kernels ----------------
__global__ void prep_small(const float* __restrict__ kpw, const float* __restrict__ vs,
                           const int* __restrict__ idx_map, const float* __restrict__ bias,
                           const int* __restrict__ lvl, const int* __restrict__ tivr) {
    int tid = threadIdx.x;
    if (tid < C2_*K_) {
        int d = tid / K_, k = tid % K_;
        float s0 = 0.f, s1 = 0.f, s2 = 0.f;
        for (int a = 0; a < A_; a++) {
            float w = kpw[d*36 + idx_map[k*A_ + a]];
            s0 += w * vs[a*3+0]; s1 += w * vs[a*3+1]; s2 += w * vs[a*3+2];
        }
        float inv = 1.0f / fmaxf(sqrtf(s0*s0 + s1*s1 + s2*s2), 1e-12f);
        g_kpo[tid*3+0] = s0*inv; g_kpo[tid*3+1] = s1*inv; g_kpo[tid*3+2] = s2*inv;
    }
    if (tid < C2_*A_) {
        int d = tid / A_, r = tid % A_;
        float be = 0.f;
        for (int k = 0; k < K_; k++) be += bias[d*5 + lvl[tivr[r*K_ + k]]];
        g_be[tid] = be;
    }
}

__global__ void mean_dir_kernel(const int* __restrict__ nbr, const float* __restrict__ vert) {
    int t = blockIdx.x * blockDim.x + threadIdx.x;
    if (t >= B_*P_) return;
    int b = t / P_;
    float vx = vert[t*3+0], vy = vert[t*3+1], vz = vert[t*3+2];
    float mx = 0.f, my = 0.f, mz = 0.f;
    const int* np = nbr + (size_t)t * NB_;
    const float* vb = vert + (size_t)b * P_ * 3;
    #pragma unroll 4
    for (int n = 0; n < NB_; n++) {
        int q = np[n];
        float dx = vb[q*3+0] - vx, dy = vb[q*3+1] - vy, dz = vb[q*3+2] - vz;
        float inv = 1.0f / fmaxf(sqrtf(dx*dx + dy*dy + dz*dz), 1e-12f);
        mx += dx*inv; my += dy*inv; mz += dz*inv;
    }
    const float s = 1.0f / (float)NB_;
    g_md[t*3+0] = mx*s; g_md[t*3+1] = my*s; g_md[t*3+2] = mz*s;
}

// WT -> g_WTh[k][nh][sub][ks][wn6][j2][lane][e8], fp16, mma-B fragment order.
// halves in float4 unit: {b0(nf=2j),b1(nf=2j),b0(nf=2j+1),b1(nf=2j+1)},
// b0 halves: k = 16ks + {2t,2t+1}; b1: {2t+8,2t+9}; column = wn*32 + nf*8 + g.
__global__ void prep_wt(const float* __restrict__ W, const float* __restrict__ kpw,
                        const int* __restrict__ idx_map, const int* __restrict__ tivr,
                        const int* __restrict__ tir) {
    int idx = blockIdx.x * 256 + threadIdx.x;
    if (idx >= WT_HALVES) return;
    int e    = idx & 7;  int u = idx >> 3;
    int lane = u & 31;   u >>= 5;
    int j    = u & 1;    u >>= 1;
    int wn   = u % 6;    u /= 6;
    int ks   = u % 3;    u /= 3;
    int sub  = u & 7;    u >>= 3;
    int nh   = u & 1;
    int k    = u >> 1;
    int g = lane >> 2, t = lane & 3;
    int nf   = 2*j + (e >> 2);
    int koff = e & 3;
    int ca = sub*48 + ks*16 + 2*t + (koff & 1) + 8*(koff >> 1);
    int c = ca / A_, a = ca - c*A_;
    int col = wn*32 + nf*8 + g;
    int d = nh*16 + (col/48)*4 + (col & 3);
    int r = (col % 48) >> 2;
    int m = idx_map[tivr[r*K_ + k]*A_ + tir[r*A_ + a]];
    g_WTh[idx] = __float2half_rn(W[(d*C1_ + c)*36 + m] * kpw[d*36 + m]);
}

// ---------------- main kernel ----------------
// grid = 256 = b(2) x ptile(64) x nh(2); block = 768
__global__ void __launch_bounds__(NTHR_, 1)
main_kernel(const float* __restrict__ fm, float* __restrict__ out) {
    extern __shared__ char smc[];
    float* sAcc = (float*)(smc + SACC_B);

    const int tid  = threadIdx.x;
    const int wid  = tid >> 5;
    const int lane = tid & 31;
    const int wm = wid & 3, wn = wid >> 2;     // wm: 32-row group; wn: 32-col group (0..5)
    const int g = lane >> 2, t = lane & 3;
    const int nh = blockIdx.x & 1;
    const int pt = blockIdx.x >> 1;
    const int b  = pt >> 6;
    const int p0 = (pt & 63) << 7;

    for (int i = tid; i < 128*196; i += NTHR_) sAcc[i] = 0.f;

    float part[2][4][4];
    #pragma unroll
    for (int mf = 0; mf < 2; mf++)
        #pragma unroll
        for (int nf = 0; nf < 4; nf++)
            #pragma unroll
            for (int c = 0; c < 4; c++) part[mf][nf][c] = 0.f;

    // ---- A loader (threads 0..511): LDG f32 -> pack half2 -> STS ----
    const int clA = tid & 3;
    const int pA  = tid >> 2;
    const bool aActive = (tid < 512);
    uint32_t hA[6];

    auto ldgA = [&](int s) {
        if (!aActive) return;
        const int k = s >> 3, sub = s & 7;
        const float* src = fm + (((size_t)(b*C1_ + sub*4 + clA)*K_ + k)*P_ + p0 + pA)*A_;
        float4 v0 = ((const float4*)src)[0];
        float4 v1 = ((const float4*)src)[1];
        float4 v2 = ((const float4*)src)[2];
        hA[0] = packh2(v0.x, v0.y); hA[1] = packh2(v0.z, v0.w);
        hA[2] = packh2(v1.x, v1.y); hA[3] = packh2(v1.z, v1.w);
        hA[4] = packh2(v2.x, v2.y); hA[5] = packh2(v2.z, v2.w);
    };
    auto stsA = [&](int s) {
        if (!aActive) return;
        char* d = smc + SA_B + (s & 1)*14336 + pA*112 + clA*24;
        ((uint2*)d)[0] = make_uint2(hA[0], hA[1]);
        ((uint2*)d)[1] = make_uint2(hA[2], hA[3]);
        ((uint2*)d)[2] = make_uint2(hA[4], hA[5]);
    };
    auto cpB = [&](int s) {
        const int k = s >> 3, sub = s & 7;
        const __half* src = g_WTh + ((size_t)((k*2 + nh)*8 + sub))*9216;
        char* dst = smc + SB_B + (s % 3)*18432;
        cp16(dst + tid*16, src + tid*8);
        {
            int u = tid + NTHR_;
            if (u < 1152) cp16(dst + u*16, src + u*8);
        }
    };

    // prologue
    ldgA(0); stsA(0);
    ldgA(1);
    cpB(0); CP_COMMIT();
    cpB(1); CP_COMMIT();

    const uint32_t aSm = smem_addr(smc);    // base smem addr
    // per-lane ldmatrix row address pieces (constant across steps)
    const uint32_t aRowOff = (uint32_t)((wm*32 + (lane & 15))*112 + (lane >> 4)*16);

    for (int s = 0; s < STEPS2_; s++) {
        CP_WAIT1();
        __syncthreads();

        if (s + 1 < STEPS2_) {
            stsA(s + 1);
            if (s + 2 < STEPS2_) ldgA(s + 2);
        }
        if (s + 2 < STEPS2_) cpB(s + 2);
        CP_COMMIT();

        const uint32_t aBase = aSm + SA_B + (uint32_t)(s & 1)*14336 + aRowOff;
        const float4*  B4 = (const float4*)(smc + SB_B + (s % 3)*18432) + wn*64 + lane;

        #pragma unroll
        for (int ks = 0; ks < 3; ks++) {
            uint32_t a0[4], a1[4];
            ldsm4(a0, aBase + ks*32);
            ldsm4(a1, aBase + 16*112 + ks*32);
            const float4* Bq = B4 + ks*384;
            float4 q0 = Bq[0];        // j=0: nf 0,1
            float4 q1 = Bq[32];       // j=1: nf 2,3
            mma16(part[0][0], a0, __float_as_uint(q0.x), __float_as_uint(q0.y));
            mma16(part[1][0], a1, __float_as_uint(q0.x), __float_as_uint(q0.y));
            mma16(part[0][1], a0, __float_as_uint(q0.z), __float_as_uint(q0.w));
            mma16(part[1][1], a1, __float_as_uint(q0.z), __float_as_uint(q0.w));
            mma16(part[0][2], a0, __float_as_uint(q1.x), __float_as_uint(q1.y));
            mma16(part[1][2], a1, __float_as_uint(q1.x), __float_as_uint(q1.y));
            mma16(part[0][3], a0, __float_as_uint(q1.z), __float_as_uint(q1.w));
            mma16(part[1][3], a1, __float_as_uint(q1.z), __float_as_uint(q1.w));
        }

        if ((s & 7) == 7) {
            const int k = s >> 3;
            // load md for this thread's 4 rows (L1-hot)
            float md[2][2][3];
            #pragma unroll
            for (int mf = 0; mf < 2; mf++)
                #pragma unroll
                for (int h = 0; h < 2; h++) {
                    const float* mp = g_md + ((size_t)b*P_ + p0 + wm*32 + mf*16 + g + 8*h)*3;
                    md[mf][h][0] = mp[0]; md[mf][h][1] = mp[1]; md[mf][h][2] = mp[2];
                }
            #pragma unroll
            for (int nf = 0; nf < 4; nf++) {
                #pragma unroll
                for (int e = 0; e < 2; e++) {
                    int col = wn*32 + nf*8 + 2*t + e;
                    int d = nh*16 + (col/48)*4 + (col & 3);
                    const float* q = g_kpo + (d*K_ + k)*3;
                    float k0 = q[0], k1 = q[1], k2 = q[2];
                    #pragma unroll
                    for (int mf = 0; mf < 2; mf++)
                        #pragma unroll
                        for (int h = 0; h < 2; h++) {
                            float pw = fmaxf(md[mf][h][0]*k0 + md[mf][h][1]*k1
                                           + md[mf][h][2]*k2, 0.f);
                            int row = wm*32 + mf*16 + g + 8*h;
                            sAcc[row*196 + col] += pw * part[mf][nf][2*h + e];
                            part[mf][nf][2*h + e] = (e == 1 && h == 1) ? 0.f
                                                   : part[mf][nf][2*h + e];
                        }
                }
                #pragma unroll
                for (int c = 0; c < 4; c++) part[0][nf][c] = 0.f, part[1][nf][c] = 0.f;
            }
        }
    }

    __syncthreads();

    // coalesced store: 2048 (d,p) pairs, 12 contiguous floats each
    #pragma unroll
    for (int i = 0; i < 3; i++) {
        int pair = i*NTHR_ + tid;
        if (pair >= 2048) break;
        int p  = pair & 127;
        int dl = pair >> 7;                 // 0..15
        int d  = nh*16 + dl;
        const float* ar = sAcc + p*196 + (dl >> 2)*48 + (dl & 3);
        float* op = out + (((size_t)b*C2_ + d)*P_ + p0 + p)*A_;
        float v[12];
        #pragma unroll
        for (int r = 0; r < 12; r++)
            v[r] = fmaxf(ar[r*4] + g_be[d*A_ + r], 0.f);
        reinterpret_cast<float4*>(op)[0] = make_float4(v[0], v[1], v[2],  v[3]);
        reinterpret_cast<float4*>(op)[1] = make_float4(v[4], v[5], v[6],  v[7]);
        reinterpret_cast<float4*>(op)[2] = make_float4(v[8], v[9], v[10], v[11]);
    }
}

// ---------------- launcher ----------------
extern "C" void kernel_launch(void* const* d_in, const int* in_sizes, int n_in,
                              void* d_out, int out_size) {
    const int*   nbr     = (const int*)  d_in[0];
    const float* vert    = (const float*)d_in[1];
    const float* fm      = (const float*)d_in[2];
    const float* W       = (const float*)d_in[3];
    const float* bias    = (const float*)d_in[4];
    const float* kpw     = (const float*)d_in[5];
    const float* vs      = (const float*)d_in[6];
    const int*   idx_map = (const int*)  d_in[7];
    const int*   tivr    = (const int*)  d_in[8];
    const int*   tir     = (const int*)  d_in[9];
    const int*   lvl     = (const int*)  d_in[10];
    float*       out     = (float*)d_out;

    prep_small<<<1, 512>>>(kpw, vs, idx_map, bias, lvl, tivr);
    prep_wt<<<(WT_HALVES + 255)/256, 256>>>(W, kpw, idx_map, tivr, tir);
    mean_dir_kernel<<<(B_*P_ + 255)/256, 256>>>(nbr, vert);

    cudaFuncSetAttribute(main_kernel, cudaFuncAttributeMaxDynamicSharedMemorySize, SMEM_BYTES);
    main_kernel<<<256, NTHR_, SMEM_BYTES>>>(fm, out);
}